// round 2
// baseline (speedup 1.0000x reference)
#include <cuda_runtime.h>

// ---------------------------------------------------------------------------
// LaneATT fused pipeline
//   B=32 batches, A=1000 anchors, C=64, H=12, W=20, CH=C*H=768
//   1) precompute combined gather index (batch-invariant)
//   2) gather feats[b,a,ch] from feature volumes
//   3) GEMM1: scores = feats @ W_att + b_att          (32000 x 999, K=768)
//   4) softmax over last dim (999), in place
//   5) GEMM2: out[b] = attn[b] @ feats[b]             (1000 x 768, K=1000)
//      attn[b,i,j] = (j==i) ? 0 : scores[b,i, j - (j>i)]   (eye-shift in loader)
// ---------------------------------------------------------------------------

static constexpr int Bn  = 32;
static constexpr int An  = 1000;
static constexpr int Cn  = 64;
static constexpr int Hn  = 12;
static constexpr int Wn  = 20;
static constexpr int CHn = Cn * Hn;       // 768
static constexpr int NSC = An - 1;        // 999
static constexpr int FVB = Cn * Hn * Wn;  // 15360 floats per batch volume
static constexpr int Mtot = Bn * An;      // 32000 rows for GEMM1

// Scratch (device globals: allocation-free rule)
__device__ float g_feats[Bn * An * CHn];    // ~98.3 MB
__device__ float g_scores[Bn * An * NSC];   // ~127.9 MB
__device__ int   g_comb[An * CHn];          // 3 MB

// ---------------------------------------------------------------------------
// 1) precompute combined index: comb[a*CH + c*H + h] = invalid ? -1 : z*H*W + y*W + x
// ---------------------------------------------------------------------------
__global__ void k_precomp(const int* __restrict__ z, const int* __restrict__ y,
                          const int* __restrict__ x, const int* __restrict__ inv) {
    int i = blockIdx.x * blockDim.x + threadIdx.x;
    if (i >= An * CHn) return;
    g_comb[i] = inv[i] ? -1 : (z[i] * (Hn * Wn) + y[i] * Wn + x[i]);
}

// ---------------------------------------------------------------------------
// 2) gather feats
// ---------------------------------------------------------------------------
__global__ void k_gather(const float* __restrict__ fv) {
    int a = blockIdx.x;
    int b = blockIdx.y;
    const float* fvb = fv + b * FVB;
    const int*   cmb = g_comb + a * CHn;
    float*       out = g_feats + ((long)b * An + a) * CHn;
    for (int ch = threadIdx.x; ch < CHn; ch += blockDim.x) {
        int idx = cmb[ch];
        out[ch] = (idx < 0) ? 0.0f : __ldg(fvb + idx);
    }
}

// ---------------------------------------------------------------------------
// Tiled SGEMM parameters (shared by both GEMMs)
// ---------------------------------------------------------------------------
static constexpr int BM = 128;
static constexpr int BN = 128;
static constexpr int BK = 16;
// 256 threads, 8x8 micro-tile per thread

// ---------------------------------------------------------------------------
// 3) GEMM1: g_scores[m,n] = sum_k g_feats[m,k]*W[k,n] + bias[n]
//    M=32000 (mult of 128), N=999 (guarded), K=768 (mult of 16)
// ---------------------------------------------------------------------------
__global__ __launch_bounds__(256) void k_gemm1(const float* __restrict__ Wt,
                                               const float* __restrict__ bias) {
    __shared__ float As[BK][BM];
    __shared__ float Bs[BK][BN];

    int tid = threadIdx.x;
    int m0 = blockIdx.y * BM;
    int n0 = blockIdx.x * BN;
    int tx = tid & 15;   // n direction
    int ty = tid >> 4;   // m direction

    float acc[8][8];
#pragma unroll
    for (int i = 0; i < 8; i++)
#pragma unroll
        for (int j = 0; j < 8; j++) acc[i][j] = 0.0f;

    for (int k0 = 0; k0 < CHn; k0 += BK) {
        // A tile: 128 rows x 16 cols (float4, transposed into As[k][m])
        {
            int r = tid >> 2;          // 0..63
            int c = (tid & 3) * 4;     // 0,4,8,12
#pragma unroll
            for (int rr = 0; rr < 2; rr++) {
                int row = r + rr * 64;
                float4 v = *reinterpret_cast<const float4*>(
                    g_feats + (long)(m0 + row) * CHn + k0 + c);
                As[c + 0][row] = v.x;
                As[c + 1][row] = v.y;
                As[c + 2][row] = v.z;
                As[c + 3][row] = v.w;
            }
        }
        // B tile: 16 rows x 128 cols (scalar, N guard)
        {
#pragma unroll
            for (int i = 0; i < 8; i++) {
                int e = tid + i * 256;
                int r = e >> 7;
                int c = e & 127;
                int n = n0 + c;
                Bs[r][c] = (n < NSC) ? __ldg(Wt + (long)(k0 + r) * NSC + n) : 0.0f;
            }
        }
        __syncthreads();

#pragma unroll
        for (int k = 0; k < BK; k++) {
            float a[8], bb[8];
            *reinterpret_cast<float4*>(&a[0]) = *reinterpret_cast<float4*>(&As[k][ty * 8]);
            *reinterpret_cast<float4*>(&a[4]) = *reinterpret_cast<float4*>(&As[k][ty * 8 + 4]);
            *reinterpret_cast<float4*>(&bb[0]) = *reinterpret_cast<float4*>(&Bs[k][tx * 8]);
            *reinterpret_cast<float4*>(&bb[4]) = *reinterpret_cast<float4*>(&Bs[k][tx * 8 + 4]);
#pragma unroll
            for (int i = 0; i < 8; i++)
#pragma unroll
                for (int j = 0; j < 8; j++)
                    acc[i][j] = fmaf(a[i], bb[j], acc[i][j]);
        }
        __syncthreads();
    }

#pragma unroll
    for (int i = 0; i < 8; i++) {
        int m = m0 + ty * 8 + i;
#pragma unroll
        for (int j = 0; j < 8; j++) {
            int n = n0 + tx * 8 + j;
            if (n < NSC) g_scores[(long)m * NSC + n] = acc[i][j] + __ldg(bias + n);
        }
    }
}

// ---------------------------------------------------------------------------
// 4) softmax over NSC=999, in place, one block per row
// ---------------------------------------------------------------------------
__global__ __launch_bounds__(256) void k_softmax() {
    int row = blockIdx.x;
    float* s = g_scores + (long)row * NSC;
    int tid = threadIdx.x;
    __shared__ float red[8];

    float mx = -3.4e38f;
    for (int c = tid; c < NSC; c += 256) mx = fmaxf(mx, s[c]);
#pragma unroll
    for (int o = 16; o; o >>= 1) mx = fmaxf(mx, __shfl_xor_sync(0xffffffffu, mx, o));
    if ((tid & 31) == 0) red[tid >> 5] = mx;
    __syncthreads();
    mx = red[0];
#pragma unroll
    for (int w = 1; w < 8; w++) mx = fmaxf(mx, red[w]);
    __syncthreads();

    float sum = 0.0f;
    for (int c = tid; c < NSC; c += 256) {
        float e = __expf(s[c] - mx);
        s[c] = e;
        sum += e;
    }
#pragma unroll
    for (int o = 16; o; o >>= 1) sum += __shfl_xor_sync(0xffffffffu, sum, o);
    if ((tid & 31) == 0) red[tid >> 5] = sum;
    __syncthreads();
    float tot = red[0];
#pragma unroll
    for (int w = 1; w < 8; w++) tot += red[w];

    float inv = 1.0f / tot;
    for (int c = tid; c < NSC; c += 256) s[c] *= inv;
}

// ---------------------------------------------------------------------------
// 5) GEMM2 per batch: out[b,i,n] = sum_j attn[b,i,j] * feats[b,j,n]
//    M=1000 (guard), N=768 (mult of 128), K=1000 (guard), eye-shift in A loader
// ---------------------------------------------------------------------------
__global__ __launch_bounds__(256) void k_gemm2(float* __restrict__ out) {
    __shared__ float As[BK][BM];
    __shared__ float Bs[BK][BN];

    int tid = threadIdx.x;
    int b  = blockIdx.z;
    int m0 = blockIdx.y * BM;
    int n0 = blockIdx.x * BN;
    int tx = tid & 15;
    int ty = tid >> 4;

    const float* Sb = g_scores + (long)b * An * NSC;
    const float* Fb = g_feats + (long)b * An * CHn;

    float acc[8][8];
#pragma unroll
    for (int i = 0; i < 8; i++)
#pragma unroll
        for (int j = 0; j < 8; j++) acc[i][j] = 0.0f;

    for (int k0 = 0; k0 < An; k0 += BK) {
        // A tile = attn[i, j]: 128 rows (i) x 16 cols (j), scalar with shift
        {
#pragma unroll
            for (int i = 0; i < 8; i++) {
                int e = tid + i * 256;
                int c = e & 15;        // j offset
                int r = e >> 4;        // i offset
                int row = m0 + r;
                int j   = k0 + c;
                float v = 0.0f;
                if (row < An && j < An && j != row)
                    v = __ldg(Sb + (long)row * NSC + j - (j > row));
                As[c][r] = v;
            }
        }
        // B tile = feats[j, n]: 16 rows (j) x 128 cols (n), float4 with j guard
        {
#pragma unroll
            for (int i = 0; i < 2; i++) {
                int f = tid + i * 256;
                int r = f >> 5;
                int c = (f & 31) * 4;
                int j = k0 + r;
                float4 v = make_float4(0.f, 0.f, 0.f, 0.f);
                if (j < An)
                    v = *reinterpret_cast<const float4*>(Fb + (long)j * CHn + n0 + c);
                *reinterpret_cast<float4*>(&Bs[r][c]) = v;
            }
        }
        __syncthreads();

#pragma unroll
        for (int k = 0; k < BK; k++) {
            float a[8], bb[8];
            *reinterpret_cast<float4*>(&a[0]) = *reinterpret_cast<float4*>(&As[k][ty * 8]);
            *reinterpret_cast<float4*>(&a[4]) = *reinterpret_cast<float4*>(&As[k][ty * 8 + 4]);
            *reinterpret_cast<float4*>(&bb[0]) = *reinterpret_cast<float4*>(&Bs[k][tx * 8]);
            *reinterpret_cast<float4*>(&bb[4]) = *reinterpret_cast<float4*>(&Bs[k][tx * 8 + 4]);
#pragma unroll
            for (int i = 0; i < 8; i++)
#pragma unroll
                for (int j = 0; j < 8; j++)
                    acc[i][j] = fmaf(a[i], bb[j], acc[i][j]);
        }
        __syncthreads();
    }

#pragma unroll
    for (int i = 0; i < 8; i++) {
        int m = m0 + ty * 8 + i;
        if (m < An) {
#pragma unroll
            for (int j = 0; j < 2; j++) {
                float4 v = make_float4(acc[i][j * 4 + 0], acc[i][j * 4 + 1],
                                       acc[i][j * 4 + 2], acc[i][j * 4 + 3]);
                *reinterpret_cast<float4*>(
                    out + ((long)b * An + m) * CHn + n0 + tx * 8 + j * 4) = v;
            }
        }
    }
}

// ---------------------------------------------------------------------------
// launch
// ---------------------------------------------------------------------------
extern "C" void kernel_launch(void* const* d_in, const int* in_sizes, int n_in,
                              void* d_out, int out_size) {
    const float* fv   = (const float*)d_in[0];
    const int*   z    = (const int*)d_in[1];
    const int*   y    = (const int*)d_in[2];
    const int*   x    = (const int*)d_in[3];
    const int*   inv  = (const int*)d_in[4];
    const float* Wt   = (const float*)d_in[5];
    const float* bias = (const float*)d_in[6];
    float* out = (float*)d_out;

    k_precomp<<<(An * CHn + 255) / 256, 256>>>(z, y, x, inv);
    k_gather<<<dim3(An, Bn), 256>>>(fv);
    k_gemm1<<<dim3((NSC + BN - 1) / BN, Mtot / BM), 256>>>(Wt, bias);
    k_softmax<<<Bn * An, 256>>>();
    k_gemm2<<<dim3(CHn / BN, (An + BM - 1) / BM, Bn), 256>>>(out);
}

// round 4
// speedup vs baseline: 2.4947x; 2.4947x over previous
#include <cuda_runtime.h>
#include <cstdint>

// ---------------------------------------------------------------------------
// LaneATT fused pipeline — tensor-core (tf32 mma.sync) edition, alignment-fixed
//   B=32, A=1000, C=64, H=12, W=20, CH=768, NSC=999
//   0) pad W (stride 999 -> 1024) so GEMM1 B loads are float4-aligned
//   1) precompute combined gather index (batch-invariant)
//   2) gather feats[b,a,ch]
//   3) GEMM1 (tf32 MMA): scores = feats @ W_att + b_att   (32000 x 999, K=768)
//   4) softmax over last dim (999), in place
//   5) GEMM2 (tf32 MMA): out[b] = attn[b] @ feats[b]      (1000 x 768, K=1000)
//      attn[b,i,j] = (j==i) ? 0 : scores[b,i, j-(j>i)]    (eye-shift in loader)
// ---------------------------------------------------------------------------

static constexpr int Bn  = 32;
static constexpr int An  = 1000;
static constexpr int Cn  = 64;
static constexpr int Hn  = 12;
static constexpr int Wn  = 20;
static constexpr int CHn = Cn * Hn;       // 768
static constexpr int NSC = An - 1;        // 999
static constexpr int NPAD = 1024;         // padded N stride for W
static constexpr int FVB = Cn * Hn * Wn;  // 15360
static constexpr int Mtot = Bn * An;      // 32000

__device__ float g_feats[Bn * An * CHn];
__device__ float g_scores[Bn * An * NSC];
__device__ float g_Wpad[CHn * NPAD];
__device__ int   g_comb[An * CHn];

// ---------------------------------------------------------------------------
__global__ void k_precomp(const int* __restrict__ z, const int* __restrict__ y,
                          const int* __restrict__ x, const int* __restrict__ inv) {
    int i = blockIdx.x * blockDim.x + threadIdx.x;
    if (i >= An * CHn) return;
    g_comb[i] = inv[i] ? -1 : (z[i] * (Hn * Wn) + y[i] * Wn + x[i]);
}

// pad W: [CHn, NSC] (stride 999) -> [CHn, NPAD] (stride 1024, zero tail)
__global__ void k_padW(const float* __restrict__ Wt) {
    int i = blockIdx.x * blockDim.x + threadIdx.x;
    if (i >= CHn * NPAD) return;
    int k = i >> 10;        // / NPAD
    int n = i & (NPAD - 1);
    g_Wpad[i] = (n < NSC) ? __ldg(Wt + (long)k * NSC + n) : 0.0f;
}

__global__ void k_gather(const float* __restrict__ fv) {
    int a = blockIdx.x;
    int b = blockIdx.y;
    const float* fvb = fv + b * FVB;
    const int*   cmb = g_comb + a * CHn;
    float*       out = g_feats + ((long)b * An + a) * CHn;
    for (int ch = threadIdx.x; ch < CHn; ch += blockDim.x) {
        int idx = cmb[ch];
        out[ch] = (idx < 0) ? 0.0f : __ldg(fvb + idx);
    }
}

// ---------------------------------------------------------------------------
// tf32 helpers
// ---------------------------------------------------------------------------
__device__ __forceinline__ uint32_t f2tf(float f) {
    uint32_t r;
    asm("cvt.rna.tf32.f32 %0, %1;" : "=r"(r) : "f"(f));
    return r;
}

__device__ __forceinline__ void mma8(float* c, const uint32_t* a, const uint32_t* b) {
    asm volatile(
        "mma.sync.aligned.m16n8k8.row.col.f32.tf32.tf32.f32 "
        "{%0,%1,%2,%3}, {%4,%5,%6,%7}, {%8,%9}, {%0,%1,%2,%3};\n"
        : "+f"(c[0]), "+f"(c[1]), "+f"(c[2]), "+f"(c[3])
        : "r"(a[0]), "r"(a[1]), "r"(a[2]), "r"(a[3]), "r"(b[0]), "r"(b[1]));
}

// Tile config: block 128x128, K-tile 32, 8 warps (2x4), warp tile 64x32
static constexpr int BM = 128;
static constexpr int BN = 128;
static constexpr int BK = 32;
static constexpr int AS_STRIDE = BK + 4;   // 36: banks (4*row + k) -> conflict-free
static constexpr int BS_STRIDE = BN + 8;   // 136: banks (8*k + n) -> conflict-free

// ---------------------------------------------------------------------------
// GEMM1: scores[m,n] = feats[m,:] @ Wpad[:,n] + bias[n]
//   M=32000 (mult 128), N via padded stride 1024, K=768 (mult 32)
// ---------------------------------------------------------------------------
__global__ __launch_bounds__(256, 2) void k_gemm1(const float* __restrict__ bias) {
    __shared__ uint32_t As[BM * AS_STRIDE];
    __shared__ uint32_t Bs[BK * BS_STRIDE];

    const int tid  = threadIdx.x;
    const int warp = tid >> 5, lane = tid & 31;
    const int wm = warp >> 2, wn = warp & 3;   // 2 x 4 warp grid
    const int g = lane >> 2, t = lane & 3;
    const int m0 = blockIdx.y * BM;
    const int n0 = blockIdx.x * BN;

    float acc[4][4][4];
#pragma unroll
    for (int i = 0; i < 4; i++)
#pragma unroll
        for (int j = 0; j < 4; j++)
#pragma unroll
            for (int v = 0; v < 4; v++) acc[i][j][v] = 0.0f;

    for (int k0 = 0; k0 < CHn; k0 += BK) {
        // A: 128x32 float4 loads (stride 768, aligned), cvt to tf32
        {
            int r = tid >> 3;            // 0..31
            int c = (tid & 7) * 4;       // 0..28
#pragma unroll
            for (int rr = 0; rr < 4; rr++) {
                int row = r + rr * 32;
                float4 v = *reinterpret_cast<const float4*>(
                    g_feats + (long)(m0 + row) * CHn + k0 + c);
                uint32_t* d = &As[row * AS_STRIDE + c];
                d[0] = f2tf(v.x); d[1] = f2tf(v.y); d[2] = f2tf(v.z); d[3] = f2tf(v.w);
            }
        }
        // B: 32x128 float4 loads from padded W (stride 1024, aligned)
        {
#pragma unroll
            for (int i = 0; i < 4; i++) {
                int s = tid + i * 256;           // 1024 float4 slots
                int kr = s >> 5;
                int nq = (s & 31) * 4;
                float4 v = *reinterpret_cast<const float4*>(
                    g_Wpad + (long)(k0 + kr) * NPAD + n0 + nq);
                uint32_t* d = &Bs[kr * BS_STRIDE + nq];
                d[0] = f2tf(v.x); d[1] = f2tf(v.y); d[2] = f2tf(v.z); d[3] = f2tf(v.w);
            }
        }
        __syncthreads();

#pragma unroll
        for (int kk = 0; kk < 4; kk++) {
            int kb = kk * 8;
            uint32_t af[4][4], bf[4][2];
#pragma unroll
            for (int mt = 0; mt < 4; mt++) {
                int row = wm * 64 + mt * 16 + g;
                af[mt][0] = As[row * AS_STRIDE + kb + t];
                af[mt][1] = As[(row + 8) * AS_STRIDE + kb + t];
                af[mt][2] = As[row * AS_STRIDE + kb + t + 4];
                af[mt][3] = As[(row + 8) * AS_STRIDE + kb + t + 4];
            }
#pragma unroll
            for (int nt = 0; nt < 4; nt++) {
                int nn = wn * 32 + nt * 8 + g;
                bf[nt][0] = Bs[(kb + t) * BS_STRIDE + nn];
                bf[nt][1] = Bs[(kb + t + 4) * BS_STRIDE + nn];
            }
#pragma unroll
            for (int mt = 0; mt < 4; mt++)
#pragma unroll
                for (int nt = 0; nt < 4; nt++)
                    mma8(acc[mt][nt], af[mt], bf[nt]);
        }
        __syncthreads();
    }

    // epilogue: c0 (g, 2t), c1 (g, 2t+1), c2 (g+8, 2t), c3 (g+8, 2t+1)
#pragma unroll
    for (int mt = 0; mt < 4; mt++) {
#pragma unroll
        for (int nt = 0; nt < 4; nt++) {
            int row = m0 + wm * 64 + mt * 16 + g;
            int col = n0 + wn * 32 + nt * 8 + t * 2;
#pragma unroll
            for (int half = 0; half < 2; half++) {
                int r = row + half * 8;
#pragma unroll
                for (int cc = 0; cc < 2; cc++) {
                    int n = col + cc;
                    if (n < NSC)
                        g_scores[(long)r * NSC + n] =
                            acc[mt][nt][half * 2 + cc] + __ldg(bias + n);
                }
            }
        }
    }
}

// ---------------------------------------------------------------------------
// softmax over NSC=999, in place, one block per row
// ---------------------------------------------------------------------------
__global__ __launch_bounds__(256) void k_softmax() {
    int row = blockIdx.x;
    float* s = g_scores + (long)row * NSC;
    int tid = threadIdx.x;
    __shared__ float red[8];

    float mx = -3.4e38f;
    for (int c = tid; c < NSC; c += 256) mx = fmaxf(mx, s[c]);
#pragma unroll
    for (int o = 16; o; o >>= 1) mx = fmaxf(mx, __shfl_xor_sync(0xffffffffu, mx, o));
    if ((tid & 31) == 0) red[tid >> 5] = mx;
    __syncthreads();
    mx = red[0];
#pragma unroll
    for (int w = 1; w < 8; w++) mx = fmaxf(mx, red[w]);
    __syncthreads();

    float sum = 0.0f;
    for (int c = tid; c < NSC; c += 256) {
        float e = __expf(s[c] - mx);
        s[c] = e;
        sum += e;
    }
#pragma unroll
    for (int o = 16; o; o >>= 1) sum += __shfl_xor_sync(0xffffffffu, sum, o);
    if ((tid & 31) == 0) red[tid >> 5] = sum;
    __syncthreads();
    float tot = red[0];
#pragma unroll
    for (int w = 1; w < 8; w++) tot += red[w];

    float inv = 1.0f / tot;
    for (int c = tid; c < NSC; c += 256) s[c] *= inv;
}

// ---------------------------------------------------------------------------
// GEMM2 per batch: out[b,i,n] = sum_j attn[b,i,j] * feats[b,j,n]
//   M=1000 (guard), N=768, K=1000 (guard), eye-shift in A loader (scalar loads)
// ---------------------------------------------------------------------------
__global__ __launch_bounds__(256, 2) void k_gemm2(float* __restrict__ out) {
    __shared__ uint32_t As[BM * AS_STRIDE];
    __shared__ uint32_t Bs[BK * BS_STRIDE];

    const int tid  = threadIdx.x;
    const int warp = tid >> 5, lane = tid & 31;
    const int wm = warp >> 2, wn = warp & 3;
    const int g = lane >> 2, t = lane & 3;
    const int b  = blockIdx.z;
    const int m0 = blockIdx.y * BM;
    const int n0 = blockIdx.x * BN;

    const float* Sb = g_scores + (long)b * An * NSC;
    const float* Fb = g_feats + (long)b * An * CHn;

    float acc[4][4][4];
#pragma unroll
    for (int i = 0; i < 4; i++)
#pragma unroll
        for (int j = 0; j < 4; j++)
#pragma unroll
            for (int v = 0; v < 4; v++) acc[i][j][v] = 0.0f;

    for (int k0 = 0; k0 < An; k0 += BK) {
        // A = attn tile: 128 rows (i) x 32 cols (j), eye-shift, scalar (stride 999)
        {
#pragma unroll
            for (int e0 = 0; e0 < 16; e0++) {
                int e = tid + e0 * 256;        // 4096 scalars
                int r = e >> 5;
                int c = e & 31;
                int i = m0 + r;
                int j = k0 + c;
                float v = 0.0f;
                if (i < An && j < An && j != i)
                    v = __ldg(Sb + (long)i * NSC + j - (j > i));
                As[r * AS_STRIDE + c] = f2tf(v);
            }
        }
        // B = feats tile: 32 rows (j) x 128 cols (n), float4 (stride 768), j guard
        {
#pragma unroll
            for (int i = 0; i < 4; i++) {
                int s = tid + i * 256;
                int kr = s >> 5;
                int nq = (s & 31) * 4;
                int j = k0 + kr;
                float4 v = make_float4(0.f, 0.f, 0.f, 0.f);
                if (j < An)
                    v = *reinterpret_cast<const float4*>(Fb + (long)j * CHn + n0 + nq);
                uint32_t* d = &Bs[kr * BS_STRIDE + nq];
                d[0] = f2tf(v.x); d[1] = f2tf(v.y); d[2] = f2tf(v.z); d[3] = f2tf(v.w);
            }
        }
        __syncthreads();

#pragma unroll
        for (int kk = 0; kk < 4; kk++) {
            int kb = kk * 8;
            uint32_t af[4][4], bf[4][2];
#pragma unroll
            for (int mt = 0; mt < 4; mt++) {
                int row = wm * 64 + mt * 16 + g;
                af[mt][0] = As[row * AS_STRIDE + kb + t];
                af[mt][1] = As[(row + 8) * AS_STRIDE + kb + t];
                af[mt][2] = As[row * AS_STRIDE + kb + t + 4];
                af[mt][3] = As[(row + 8) * AS_STRIDE + kb + t + 4];
            }
#pragma unroll
            for (int nt = 0; nt < 4; nt++) {
                int nn = wn * 32 + nt * 8 + g;
                bf[nt][0] = Bs[(kb + t) * BS_STRIDE + nn];
                bf[nt][1] = Bs[(kb + t + 4) * BS_STRIDE + nn];
            }
#pragma unroll
            for (int mt = 0; mt < 4; mt++)
#pragma unroll
                for (int nt = 0; nt < 4; nt++)
                    mma8(acc[mt][nt], af[mt], bf[nt]);
        }
        __syncthreads();
    }

    // epilogue: N=768 always in-bounds; float2 stores (stride 768, even col)
#pragma unroll
    for (int mt = 0; mt < 4; mt++) {
#pragma unroll
        for (int nt = 0; nt < 4; nt++) {
            int row = m0 + wm * 64 + mt * 16 + g;
            int col = n0 + wn * 32 + nt * 8 + t * 2;
#pragma unroll
            for (int half = 0; half < 2; half++) {
                int r = row + half * 8;
                if (r < An) {
                    float2 v = make_float2(acc[mt][nt][half * 2], acc[mt][nt][half * 2 + 1]);
                    *reinterpret_cast<float2*>(out + ((long)b * An + r) * CHn + col) = v;
                }
            }
        }
    }
}

// ---------------------------------------------------------------------------
extern "C" void kernel_launch(void* const* d_in, const int* in_sizes, int n_in,
                              void* d_out, int out_size) {
    const float* fv   = (const float*)d_in[0];
    const int*   z    = (const int*)d_in[1];
    const int*   y    = (const int*)d_in[2];
    const int*   x    = (const int*)d_in[3];
    const int*   inv  = (const int*)d_in[4];
    const float* Wt   = (const float*)d_in[5];
    const float* bias = (const float*)d_in[6];
    float* out = (float*)d_out;

    k_precomp<<<(An * CHn + 255) / 256, 256>>>(z, y, x, inv);
    k_padW<<<(CHn * NPAD + 255) / 256, 256>>>(Wt);
    k_gather<<<dim3(An, Bn), 256>>>(fv);
    k_gemm1<<<dim3((NSC + BN - 1) / BN, Mtot / BM), 256>>>(bias);
    k_softmax<<<Bn * An, 256>>>();
    k_gemm2<<<dim3(CHn / BN, (An + BM - 1) / BM, Bn), 256>>>(out);
}

// round 5
// speedup vs baseline: 3.8843x; 1.5570x over previous
#include <cuda_runtime.h>
#include <cstdint>

// ---------------------------------------------------------------------------
// LaneATT — tf32 mma.sync + cp.async 2-stage pipeline edition
//   B=32, A=1000, CH=768, NSC=999
//   0) pad W (999 -> 1024 stride), tf32-round
//   1) precompute combined gather index
//   2) gather feats (tf32-rounded) into padded layout [B][1024][768]
//   3) GEMM1: scores = feats @ Wpad + bias   (M=32768 padded, N=999, K=768)
//   4) softmax -> writes padded attn [B][1024][1024] with eye-shift, tf32-rounded
//   5) GEMM2: out[b] = attn[b] @ feats[b]    (M->1000 guarded, N=768, K=1024)
// ---------------------------------------------------------------------------

static constexpr int Bn  = 32;
static constexpr int An  = 1000;
static constexpr int APAD = 1024;          // padded anchor count
static constexpr int Cn  = 64;
static constexpr int Hn  = 12;
static constexpr int Wn  = 20;
static constexpr int CHn = Cn * Hn;        // 768
static constexpr int NSC = An - 1;         // 999
static constexpr int NPAD = 1024;          // padded N stride for W / attn
static constexpr int FVB = Cn * Hn * Wn;   // 15360
static constexpr int MtotPad = Bn * APAD;  // 32768

// zero-initialized device globals; padding rows/cols are never written -> stay 0
__device__ float g_feats[Bn * APAD * CHn];    // ~100.7 MB
__device__ float g_scores[Bn * APAD * NSC];   // ~130.9 MB
__device__ float g_attn[Bn * APAD * NPAD];    // ~134.2 MB
__device__ float g_Wpad[CHn * NPAD];          // 3 MB
__device__ int   g_comb[An * CHn];            // 3 MB

// ---------------------------------------------------------------------------
__device__ __forceinline__ uint32_t f2tf(float f) {
    uint32_t r;
    asm("cvt.rna.tf32.f32 %0, %1;" : "=r"(r) : "f"(f));
    return r;
}
__device__ __forceinline__ float f2tf_f(float f) {
    return __uint_as_float(f2tf(f));
}

__device__ __forceinline__ void mma8(float* c, const uint32_t* a, const uint32_t* b) {
    asm volatile(
        "mma.sync.aligned.m16n8k8.row.col.f32.tf32.tf32.f32 "
        "{%0,%1,%2,%3}, {%4,%5,%6,%7}, {%8,%9}, {%0,%1,%2,%3};\n"
        : "+f"(c[0]), "+f"(c[1]), "+f"(c[2]), "+f"(c[3])
        : "r"(a[0]), "r"(a[1]), "r"(a[2]), "r"(a[3]), "r"(b[0]), "r"(b[1]));
}

__device__ __forceinline__ uint32_t s2u(const void* p) {
    return (uint32_t)__cvta_generic_to_shared(p);
}
__device__ __forceinline__ void cpa16(uint32_t dst, const void* src) {
    asm volatile("cp.async.cg.shared.global [%0], [%1], 16;\n" :: "r"(dst), "l"(src));
}
#define CP_COMMIT() asm volatile("cp.async.commit_group;\n" ::: "memory")
#define CP_WAIT1()  asm volatile("cp.async.wait_group 1;\n" ::: "memory")
#define CP_WAIT0()  asm volatile("cp.async.wait_group 0;\n" ::: "memory")

// ---------------------------------------------------------------------------
__global__ void k_precomp(const int* __restrict__ z, const int* __restrict__ y,
                          const int* __restrict__ x, const int* __restrict__ inv) {
    int i = blockIdx.x * blockDim.x + threadIdx.x;
    if (i >= An * CHn) return;
    g_comb[i] = inv[i] ? -1 : (z[i] * (Hn * Wn) + y[i] * Wn + x[i]);
}

__global__ void k_padW(const float* __restrict__ Wt) {
    int i = blockIdx.x * blockDim.x + threadIdx.x;
    if (i >= CHn * NPAD) return;
    int k = i >> 10;
    int n = i & (NPAD - 1);
    g_Wpad[i] = (n < NSC) ? f2tf_f(__ldg(Wt + (long)k * NSC + n)) : 0.0f;
}

__global__ void k_gather(const float* __restrict__ fv) {
    int a = blockIdx.x;
    int b = blockIdx.y;
    const float* fvb = fv + b * FVB;
    const int*   cmb = g_comb + a * CHn;
    float*       out = g_feats + ((long)b * APAD + a) * CHn;
    for (int ch = threadIdx.x; ch < CHn; ch += blockDim.x) {
        int idx = cmb[ch];
        out[ch] = (idx < 0) ? 0.0f : f2tf_f(__ldg(fvb + idx));
    }
}

// ---------------------------------------------------------------------------
// Tile config: block 128x128, K-tile 32, 8 warps (2x4), warp tile 64x32
static constexpr int BM = 128;
static constexpr int BN = 128;
static constexpr int BK = 32;
static constexpr int AS_STRIDE = BK + 4;    // 36
static constexpr int BS_STRIDE = BN + 8;    // 136
static constexpr int A_ELE = BM * AS_STRIDE;            // 4608 floats
static constexpr int B_ELE = BK * BS_STRIDE;            // 4352 floats
static constexpr int STAGE_ELE = A_ELE + B_ELE;         // 8960 floats
static constexpr int SMEM_BYTES = 2 * STAGE_ELE * 4;    // 71680 B

// ---------------------------------------------------------------------------
// GEMM1: scores[m,n] = feats[m,:] @ Wpad[:,n] + bias[n]; M=32768, K=768
// ---------------------------------------------------------------------------
__global__ __launch_bounds__(256, 2) void k_gemm1(const float* __restrict__ bias) {
    extern __shared__ float smem[];
    float* sA[2] = { smem,          smem + STAGE_ELE };
    float* sB[2] = { smem + A_ELE,  smem + STAGE_ELE + A_ELE };

    const int tid  = threadIdx.x;
    const int warp = tid >> 5, lane = tid & 31;
    const int wm = warp >> 2, wn = warp & 3;
    const int g = lane >> 2, t = lane & 3;
    const int m0 = blockIdx.y * BM;
    const int n0 = blockIdx.x * BN;

    const int ar = tid >> 3, ac = (tid & 7) * 4;   // A loader coords
    const int bkr = tid >> 5, bnq = (tid & 31) * 4; // B loader coords

    float acc[4][4][4];
#pragma unroll
    for (int i = 0; i < 4; i++)
#pragma unroll
        for (int j = 0; j < 4; j++)
#pragma unroll
            for (int v = 0; v < 4; v++) acc[i][j][v] = 0.0f;

    auto load_tile = [&](int kt, int st) {
        int k0 = kt * BK;
#pragma unroll
        for (int rr = 0; rr < 4; rr++) {
            int row = ar + rr * 32;
            cpa16(s2u(&sA[st][row * AS_STRIDE + ac]),
                  g_feats + (long)(m0 + row) * CHn + k0 + ac);
        }
#pragma unroll
        for (int i = 0; i < 4; i++) {
            int k = bkr + i * 8;
            cpa16(s2u(&sB[st][k * BS_STRIDE + bnq]),
                  g_Wpad + (long)(k0 + k) * NPAD + n0 + bnq);
        }
    };

    constexpr int NK = CHn / BK;   // 24
    load_tile(0, 0);
    CP_COMMIT();

    for (int kt = 0; kt < NK; kt++) {
        int cur = kt & 1;
        if (kt + 1 < NK) { load_tile(kt + 1, cur ^ 1); CP_COMMIT(); CP_WAIT1(); }
        else             { CP_WAIT0(); }
        __syncthreads();

        const uint32_t* As = reinterpret_cast<const uint32_t*>(sA[cur]);
        const uint32_t* Bs = reinterpret_cast<const uint32_t*>(sB[cur]);
#pragma unroll
        for (int kk = 0; kk < 4; kk++) {
            int kb = kk * 8;
            uint32_t af[4][4], bf[4][2];
#pragma unroll
            for (int mt = 0; mt < 4; mt++) {
                int row = wm * 64 + mt * 16 + g;
                af[mt][0] = As[row * AS_STRIDE + kb + t];
                af[mt][1] = As[(row + 8) * AS_STRIDE + kb + t];
                af[mt][2] = As[row * AS_STRIDE + kb + t + 4];
                af[mt][3] = As[(row + 8) * AS_STRIDE + kb + t + 4];
            }
#pragma unroll
            for (int nt = 0; nt < 4; nt++) {
                int nn = wn * 32 + nt * 8 + g;
                bf[nt][0] = Bs[(kb + t) * BS_STRIDE + nn];
                bf[nt][1] = Bs[(kb + t + 4) * BS_STRIDE + nn];
            }
#pragma unroll
            for (int mt = 0; mt < 4; mt++)
#pragma unroll
                for (int nt = 0; nt < 4; nt++)
                    mma8(acc[mt][nt], af[mt], bf[nt]);
        }
        __syncthreads();
    }

#pragma unroll
    for (int mt = 0; mt < 4; mt++) {
#pragma unroll
        for (int nt = 0; nt < 4; nt++) {
            int row = m0 + wm * 64 + mt * 16 + g;
            int col = n0 + wn * 32 + nt * 8 + t * 2;
#pragma unroll
            for (int half = 0; half < 2; half++) {
                int r = row + half * 8;
#pragma unroll
                for (int cc = 0; cc < 2; cc++) {
                    int n = col + cc;
                    if (n < NSC)
                        g_scores[(long)r * NSC + n] =
                            acc[mt][nt][half * 2 + cc] + __ldg(bias + n);
                }
            }
        }
    }
}

// ---------------------------------------------------------------------------
// softmax over NSC=999; writes padded attn row (stride 1024) with eye-shift,
// tf32-rounded. One block per real row.
// ---------------------------------------------------------------------------
__global__ __launch_bounds__(256) void k_softmax_attn() {
    int blk = blockIdx.x;
    int b = blk / An;
    int i = blk - b * An;
    const float* s = g_scores + ((long)b * APAD + i) * NSC;
    float* arow = g_attn + ((long)b * APAD + i) * NPAD;
    int tid = threadIdx.x;
    __shared__ float red[8];

    // pass 1: max
    float mx = -3.4e38f;
#pragma unroll
    for (int q = 0; q < 4; q++) {
        int c = tid + q * 256;
        if (c < NSC) mx = fmaxf(mx, s[c]);
    }
#pragma unroll
    for (int o = 16; o; o >>= 1) mx = fmaxf(mx, __shfl_xor_sync(0xffffffffu, mx, o));
    if ((tid & 31) == 0) red[tid >> 5] = mx;
    __syncthreads();
    mx = red[0];
#pragma unroll
    for (int w = 1; w < 8; w++) mx = fmaxf(mx, red[w]);
    __syncthreads();

    // pass 2: exp + sum (keep e in regs)
    float e[4];
    float sum = 0.0f;
#pragma unroll
    for (int q = 0; q < 4; q++) {
        int c = tid + q * 256;
        float v = 0.0f;
        if (c < NSC) { v = __expf(s[c] - mx); sum += v; }
        e[q] = v;
    }
#pragma unroll
    for (int o = 16; o; o >>= 1) sum += __shfl_xor_sync(0xffffffffu, sum, o);
    if ((tid & 31) == 0) red[tid >> 5] = sum;
    __syncthreads();
    float tot = red[0];
#pragma unroll
    for (int w = 1; w < 8; w++) tot += red[w];
    float inv = 1.0f / tot;

    // write attn with eye shift: column j = c + (c >= i)
#pragma unroll
    for (int q = 0; q < 4; q++) {
        int c = tid + q * 256;
        if (c < NSC) {
            int j = c + (c >= i ? 1 : 0);
            arow[j] = f2tf_f(e[q] * inv);
        }
    }
    // zero diag + padded tail
    if (tid == 0) arow[i] = 0.0f;
    if (tid >= 232 && tid < 256) arow[NPAD - 24 + (tid - 232)] = 0.0f;
}

// ---------------------------------------------------------------------------
// GEMM2: out[b,i,n] = sum_j attn[b,i,j] * feats[b,j,n]; K=1024 (padded), no guards
// ---------------------------------------------------------------------------
__global__ __launch_bounds__(256, 2) void k_gemm2(float* __restrict__ out) {
    extern __shared__ float smem[];
    float* sA[2] = { smem,          smem + STAGE_ELE };
    float* sB[2] = { smem + A_ELE,  smem + STAGE_ELE + A_ELE };

    const int tid  = threadIdx.x;
    const int warp = tid >> 5, lane = tid & 31;
    const int wm = warp >> 2, wn = warp & 3;
    const int g = lane >> 2, t = lane & 3;
    const int b  = blockIdx.z;
    const int m0 = blockIdx.y * BM;
    const int n0 = blockIdx.x * BN;

    const float* Ab = g_attn + (long)b * APAD * NPAD;
    const float* Fb = g_feats + (long)b * APAD * CHn;

    const int ar = tid >> 3, ac = (tid & 7) * 4;
    const int bkr = tid >> 5, bnq = (tid & 31) * 4;

    float acc[4][4][4];
#pragma unroll
    for (int i = 0; i < 4; i++)
#pragma unroll
        for (int j = 0; j < 4; j++)
#pragma unroll
            for (int v = 0; v < 4; v++) acc[i][j][v] = 0.0f;

    auto load_tile = [&](int kt, int st) {
        int k0 = kt * BK;
#pragma unroll
        for (int rr = 0; rr < 4; rr++) {
            int row = ar + rr * 32;
            cpa16(s2u(&sA[st][row * AS_STRIDE + ac]),
                  Ab + (long)(m0 + row) * NPAD + k0 + ac);
        }
#pragma unroll
        for (int i = 0; i < 4; i++) {
            int k = bkr + i * 8;
            cpa16(s2u(&sB[st][k * BS_STRIDE + bnq]),
                  Fb + (long)(k0 + k) * CHn + n0 + bnq);
        }
    };

    constexpr int NK = APAD / BK;  // 32
    load_tile(0, 0);
    CP_COMMIT();

    for (int kt = 0; kt < NK; kt++) {
        int cur = kt & 1;
        if (kt + 1 < NK) { load_tile(kt + 1, cur ^ 1); CP_COMMIT(); CP_WAIT1(); }
        else             { CP_WAIT0(); }
        __syncthreads();

        const uint32_t* As = reinterpret_cast<const uint32_t*>(sA[cur]);
        const uint32_t* Bs = reinterpret_cast<const uint32_t*>(sB[cur]);
#pragma unroll
        for (int kk = 0; kk < 4; kk++) {
            int kb = kk * 8;
            uint32_t af[4][4], bf[4][2];
#pragma unroll
            for (int mt = 0; mt < 4; mt++) {
                int row = wm * 64 + mt * 16 + g;
                af[mt][0] = As[row * AS_STRIDE + kb + t];
                af[mt][1] = As[(row + 8) * AS_STRIDE + kb + t];
                af[mt][2] = As[row * AS_STRIDE + kb + t + 4];
                af[mt][3] = As[(row + 8) * AS_STRIDE + kb + t + 4];
            }
#pragma unroll
            for (int nt = 0; nt < 4; nt++) {
                int nn = wn * 32 + nt * 8 + g;
                bf[nt][0] = Bs[(kb + t) * BS_STRIDE + nn];
                bf[nt][1] = Bs[(kb + t + 4) * BS_STRIDE + nn];
            }
#pragma unroll
            for (int mt = 0; mt < 4; mt++)
#pragma unroll
                for (int nt = 0; nt < 4; nt++)
                    mma8(acc[mt][nt], af[mt], bf[nt]);
        }
        __syncthreads();
    }

#pragma unroll
    for (int mt = 0; mt < 4; mt++) {
#pragma unroll
        for (int nt = 0; nt < 4; nt++) {
            int row = m0 + wm * 64 + mt * 16 + g;
            int col = n0 + wn * 32 + nt * 8 + t * 2;
#pragma unroll
            for (int half = 0; half < 2; half++) {
                int r = row + half * 8;
                if (r < An) {
                    float2 v = make_float2(acc[mt][nt][half * 2], acc[mt][nt][half * 2 + 1]);
                    *reinterpret_cast<float2*>(out + ((long)b * An + r) * CHn + col) = v;
                }
            }
        }
    }
}

// ---------------------------------------------------------------------------
extern "C" void kernel_launch(void* const* d_in, const int* in_sizes, int n_in,
                              void* d_out, int out_size) {
    const float* fv   = (const float*)d_in[0];
    const int*   z    = (const int*)d_in[1];
    const int*   y    = (const int*)d_in[2];
    const int*   x    = (const int*)d_in[3];
    const int*   inv  = (const int*)d_in[4];
    const float* Wt   = (const float*)d_in[5];
    const float* bias = (const float*)d_in[6];
    float* out = (float*)d_out;

    cudaFuncSetAttribute(k_gemm1, cudaFuncAttributeMaxDynamicSharedMemorySize, SMEM_BYTES);
    cudaFuncSetAttribute(k_gemm2, cudaFuncAttributeMaxDynamicSharedMemorySize, SMEM_BYTES);

    k_precomp<<<(An * CHn + 255) / 256, 256>>>(z, y, x, inv);
    k_padW<<<(CHn * NPAD + 255) / 256, 256>>>(Wt);
    k_gather<<<dim3(An, Bn), 256>>>(fv);
    k_gemm1<<<dim3((NSC + BN - 1) / BN, MtotPad / BM), 256, SMEM_BYTES>>>(bias);
    k_softmax_attn<<<Bn * An, 256>>>();
    k_gemm2<<<dim3(CHn / BN, APAD / BM, Bn), 256, SMEM_BYTES>>>(out);
}

// round 7
// speedup vs baseline: 6.2698x; 1.6141x over previous
#include <cuda_runtime.h>
#include <cuda_fp16.h>
#include <cstdint>

// ---------------------------------------------------------------------------
// LaneATT — fp16 mma.sync (m16n8k16) + ldmatrix + cp.async ring edition
//   B=32, A=1000 (pad 1024), CH=768, NSC=999 (pad 1024)
//   1) precompute gather index; W^T -> fp16 [n][k]; padded fp32 bias
//   2) gather feats -> fp16 [b][1024][768]; transpose -> featsT fp16 [b][768][1024]
//   3) GEMM1: scores(f32, padded 1024) = feats @ W + b    (32768 x 1024, K=768)
//   4) softmax(999) -> attn fp16 [b][1024][1024], eye-shift, diag 0, zero tail
//   5) GEMM2: out[b] = attn[b] @ feats[b]                 (1024 x 768, K=1024)
// GEMM kernels: block 128x128, BK=32(half), 8 warps (2x4), warp 64x32,
// 3-buffer cp.async ring (2 in flight), ldmatrix fragments, fp32 accum.
// ---------------------------------------------------------------------------

static constexpr int Bn  = 32;
static constexpr int An  = 1000;
static constexpr int APAD = 1024;
static constexpr int Cn  = 64;
static constexpr int Hn  = 12;
static constexpr int Wn  = 20;
static constexpr int CHn = Cn * Hn;        // 768
static constexpr int NSC = An - 1;         // 999
static constexpr int NPAD = 1024;
static constexpr int FVB = Cn * Hn * Wn;   // 15360
static constexpr int MtotPad = Bn * APAD;  // 32768

__device__ __half g_featsH[Bn * APAD * CHn];    // 48 MB  [b][a][ch]
__device__ __half g_featsTH[Bn * CHn * APAD];   // 48 MB  [b][ch][a]
__device__ __half g_attnH[Bn * APAD * NPAD];    // 64 MB  [b][i][j]
__device__ __half g_WTH[APAD * CHn];            // 1.5 MB [n][k]
__device__ float  g_scores[(long)MtotPad * NPAD]; // 134 MB padded stride
__device__ float  g_biasPad[NPAD];
__device__ int    g_comb[An * CHn];

// ---------------------------------------------------------------------------
// helpers
// ---------------------------------------------------------------------------
__device__ __forceinline__ uint32_t smem_u32(const void* p) {
    return (uint32_t)__cvta_generic_to_shared(p);
}
__device__ __forceinline__ void cpa16(uint32_t dst, const void* src) {
    asm volatile("cp.async.cg.shared.global [%0], [%1], 16;\n" :: "r"(dst), "l"(src));
}
#define CP_COMMIT() asm volatile("cp.async.commit_group;\n" ::: "memory")
#define CP_WAIT1()  asm volatile("cp.async.wait_group 1;\n" ::: "memory")
#define CP_WAIT0()  asm volatile("cp.async.wait_group 0;\n" ::: "memory")

__device__ __forceinline__ void ldsm_x4(uint32_t* r, uint32_t addr) {
    asm volatile("ldmatrix.sync.aligned.m8n8.x4.shared.b16 {%0,%1,%2,%3}, [%4];"
                 : "=r"(r[0]), "=r"(r[1]), "=r"(r[2]), "=r"(r[3]) : "r"(addr));
}
__device__ __forceinline__ void ldsm_x2(uint32_t* r, uint32_t addr) {
    asm volatile("ldmatrix.sync.aligned.m8n8.x2.shared.b16 {%0,%1}, [%2];"
                 : "=r"(r[0]), "=r"(r[1]) : "r"(addr));
}
__device__ __forceinline__ void mma16(float* c, const uint32_t* a, const uint32_t* b) {
    asm volatile(
        "mma.sync.aligned.m16n8k16.row.col.f32.f16.f16.f32 "
        "{%0,%1,%2,%3}, {%4,%5,%6,%7}, {%8,%9}, {%0,%1,%2,%3};\n"
        : "+f"(c[0]), "+f"(c[1]), "+f"(c[2]), "+f"(c[3])
        : "r"(a[0]), "r"(a[1]), "r"(a[2]), "r"(a[3]), "r"(b[0]), "r"(b[1]));
}

// ---------------------------------------------------------------------------
// prep kernels
// ---------------------------------------------------------------------------
__global__ void k_precomp(const int* __restrict__ z, const int* __restrict__ y,
                          const int* __restrict__ x, const int* __restrict__ inv) {
    int i = blockIdx.x * blockDim.x + threadIdx.x;
    if (i >= An * CHn) return;
    g_comb[i] = inv[i] ? -1 : (z[i] * (Hn * Wn) + y[i] * Wn + x[i]);
}

__global__ void k_WT(const float* __restrict__ Wt, const float* __restrict__ bias) {
    int i = blockIdx.x * blockDim.x + threadIdx.x;
    if (i >= APAD * CHn) return;
    int n = i / CHn, k = i - n * CHn;
    g_WTH[i] = (n < NSC) ? __float2half(__ldg(Wt + (long)k * NSC + n)) : __half(0.0f);
    if (i < NPAD) g_biasPad[i] = (i < NSC) ? __ldg(bias + i) : 0.0f;
}

__global__ void k_gather(const float* __restrict__ fv) {
    int a = blockIdx.x;
    int b = blockIdx.y;
    const float* fvb = fv + b * FVB;
    const int*   cmb = g_comb + a * CHn;
    __half*      out = g_featsH + ((long)b * APAD + a) * CHn;
    for (int ch = threadIdx.x; ch < CHn; ch += blockDim.x) {
        int idx = cmb[ch];
        out[ch] = (idx < 0) ? __half(0.0f) : __float2half(__ldg(fvb + idx));
    }
}

// tiled transpose featsH -> featsTH
__global__ void k_transpose() {
    __shared__ __half t[32][40];
    int b  = blockIdx.z;
    int a0 = blockIdx.x * 32;
    int c0 = blockIdx.y * 32;
    int tx = threadIdx.x, ty = threadIdx.y;       // 32 x 8
    const __half* F  = g_featsH + (long)b * APAD * CHn;
    __half*       FT = g_featsTH + (long)b * CHn * APAD;
#pragma unroll
    for (int i = 0; i < 32; i += 8)
        t[ty + i][tx] = F[(long)(a0 + ty + i) * CHn + c0 + tx];
    __syncthreads();
#pragma unroll
    for (int i = 0; i < 32; i += 8)
        FT[(long)(c0 + ty + i) * APAD + a0 + tx] = t[tx][ty + i];
}

// ---------------------------------------------------------------------------
// GEMM kernel (templated): D[128 x 128] = A[128 x K] @ B[128 x K]^T, fp16 in,
// fp32 accum. A, B both K-major. 3-buffer cp.async ring.
//   G1: A=featsH (lda=768),  B=WTH (ldb=768),  K=768  -> scores(+bias) padded
//   G2: A=attnH  (lda=1024), B=featsTH (ldb=1024), K=1024 -> out (row guard)
// ---------------------------------------------------------------------------
static constexpr int SROWB = 80;                 // smem row stride bytes (64 data + 16 pad)
static constexpr int A_TILE_B = 128 * SROWB;     // 10240
static constexpr int B_TILE_B = 128 * SROWB;     // 10240
static constexpr int STAGE_B = A_TILE_B + B_TILE_B;   // 20480
static constexpr int SMEM_G = 3 * STAGE_B;            // 61440

template <bool G1>
__global__ __launch_bounds__(256, 2) void k_gemm(float* __restrict__ out) {
    constexpr int NS = G1 ? (CHn / 32) : (APAD / 32);   // 24 / 32
    extern __shared__ char smem[];
    uint32_t sb = smem_u32(smem);

    const int tid = threadIdx.x;
    const int warp = tid >> 5, lane = tid & 31;
    const int wm = warp >> 2, wn = warp & 3;        // 2 x 4 warps
    const int m0 = blockIdx.y * 128;
    const int n0 = blockIdx.x * 128;

    const __half* Ag;
    const __half* Bg;
    int lda, ldb;
    if (G1) { Ag = g_featsH; Bg = g_WTH; lda = CHn; ldb = CHn; }
    else {
        int b = blockIdx.z;
        Ag = g_attnH + (long)b * APAD * NPAD;
        Bg = g_featsTH + (long)b * CHn * APAD;
        lda = NPAD; ldb = APAD;
    }

    // loader: 512 A-chunks + 512 B-chunks of 16B, 256 threads -> 4 each
    const int lrow = tid >> 1;               // 0..127
    const int lq   = (tid & 1) * 2;          // 0 or 2 (two 16B chunks each)
    auto load_stage = [&](int s, int buf) {
        int k0 = s * 32;                     // halves
        uint32_t ab = sb + buf * STAGE_B;
        uint32_t bb = ab + A_TILE_B;
#pragma unroll
        for (int q = 0; q < 2; q++) {
            cpa16(ab + lrow * SROWB + (lq + q) * 16,
                  Ag + (long)(m0 + lrow) * lda + k0 + (lq + q) * 8);
            cpa16(bb + lrow * SROWB + (lq + q) * 16,
                  Bg + (long)(n0 + lrow) * ldb + k0 + (lq + q) * 8);
        }
    };

    float acc[4][4][4];
#pragma unroll
    for (int i = 0; i < 4; i++)
#pragma unroll
        for (int j = 0; j < 4; j++)
#pragma unroll
            for (int v = 0; v < 4; v++) acc[i][j][v] = 0.0f;

    load_stage(0, 0); CP_COMMIT();
    load_stage(1, 1); CP_COMMIT();

    const int l15 = lane & 15;
    const int ahi = (lane >> 4) << 4;        // +16B for lanes 16..31 (k upper 8)
    const int bhi = ((lane >> 3) & 1) << 4;  // +16B for lanes 8..15

    for (int s = 0; s < NS; s++) {
        if (s + 1 < NS) CP_WAIT1(); else CP_WAIT0();
        __syncthreads();

        uint32_t ab = sb + (s % 3) * STAGE_B;
        uint32_t bb = ab + A_TILE_B;
#pragma unroll
        for (int kk = 0; kk < 2; kk++) {
            uint32_t af[4][4], bf[4][2];
#pragma unroll
            for (int mt = 0; mt < 4; mt++) {
                int row = wm * 64 + mt * 16 + l15;
                ldsm_x4(af[mt], ab + row * SROWB + kk * 32 + ahi);
            }
#pragma unroll
            for (int nt = 0; nt < 4; nt++) {
                int nr = wn * 32 + nt * 8 + (l15 & 7);
                ldsm_x2(bf[nt], bb + nr * SROWB + kk * 32 + bhi);
            }
#pragma unroll
            for (int mt = 0; mt < 4; mt++)
#pragma unroll
                for (int nt = 0; nt < 4; nt++)
                    mma16(acc[mt][nt], af[mt], bf[nt]);
        }

        if (s + 2 < NS) { load_stage(s + 2, (s + 2) % 3); CP_COMMIT(); }
    }

    // epilogue: c0,c1 -> (row g, cols 2t,2t+1); c2,c3 -> row g+8
    const int g = lane >> 2, t4 = lane & 3;
#pragma unroll
    for (int mt = 0; mt < 4; mt++) {
#pragma unroll
        for (int nt = 0; nt < 4; nt++) {
            int row = m0 + wm * 64 + mt * 16 + g;
            int col = n0 + wn * 32 + nt * 8 + t4 * 2;
            if (G1) {
                float2 bv = *reinterpret_cast<const float2*>(g_biasPad + col);
#pragma unroll
                for (int h = 0; h < 2; h++) {
                    float2 v = make_float2(acc[mt][nt][h * 2] + bv.x,
                                           acc[mt][nt][h * 2 + 1] + bv.y);
                    *reinterpret_cast<float2*>(
                        g_scores + (long)(row + h * 8) * NPAD + col) = v;
                }
            } else {
#pragma unroll
                for (int h = 0; h < 2; h++) {
                    int r = row + h * 8;
                    if (r < An) {
                        float2 v = make_float2(acc[mt][nt][h * 2], acc[mt][nt][h * 2 + 1]);
                        *reinterpret_cast<float2*>(
                            out + ((long)blockIdx.z * An + r) * CHn + col) = v;
                    }
                }
            }
        }
    }
}

// ---------------------------------------------------------------------------
// softmax over NSC=999 (padded scores stride 1024) -> fp16 attn row, eye-shift
// ---------------------------------------------------------------------------
__global__ __launch_bounds__(256) void k_softmax_attn() {
    int blk = blockIdx.x;
    int b = blk / An;
    int i = blk - b * An;
    const float* s = g_scores + ((long)b * APAD + i) * NPAD;
    __half* arow = g_attnH + ((long)b * APAD + i) * NPAD;
    int tid = threadIdx.x;
    __shared__ float red[8];

    float mx = -3.4e38f;
#pragma unroll
    for (int q = 0; q < 4; q++) {
        int c = tid + q * 256;
        if (c < NSC) mx = fmaxf(mx, s[c]);
    }
#pragma unroll
    for (int o = 16; o; o >>= 1) mx = fmaxf(mx, __shfl_xor_sync(0xffffffffu, mx, o));
    if ((tid & 31) == 0) red[tid >> 5] = mx;
    __syncthreads();
    mx = red[0];
#pragma unroll
    for (int w = 1; w < 8; w++) mx = fmaxf(mx, red[w]);
    __syncthreads();

    float e[4];
    float sum = 0.0f;
#pragma unroll
    for (int q = 0; q < 4; q++) {
        int c = tid + q * 256;
        float v = 0.0f;
        if (c < NSC) { v = __expf(s[c] - mx); sum += v; }
        e[q] = v;
    }
#pragma unroll
    for (int o = 16; o; o >>= 1) sum += __shfl_xor_sync(0xffffffffu, sum, o);
    if ((tid & 31) == 0) red[tid >> 5] = sum;
    __syncthreads();
    float tot = red[0];
#pragma unroll
    for (int w = 1; w < 8; w++) tot += red[w];
    float inv = 1.0f / tot;

#pragma unroll
    for (int q = 0; q < 4; q++) {
        int c = tid + q * 256;
        if (c < NSC) {
            int j = c + (c >= i ? 1 : 0);
            arow[j] = __float2half(e[q] * inv);
        }
    }
    if (tid == 0) arow[i] = __half(0.0f);
    if (tid >= 232 && tid < 256) arow[An + (tid - 232)] = __half(0.0f);  // 1000..1023
}

// ---------------------------------------------------------------------------
extern "C" void kernel_launch(void* const* d_in, const int* in_sizes, int n_in,
                              void* d_out, int out_size) {
    const float* fv   = (const float*)d_in[0];
    const int*   z    = (const int*)d_in[1];
    const int*   y    = (const int*)d_in[2];
    const int*   x    = (const int*)d_in[3];
    const int*   inv  = (const int*)d_in[4];
    const float* Wt   = (const float*)d_in[5];
    const float* bias = (const float*)d_in[6];
    float* out = (float*)d_out;

    cudaFuncSetAttribute(k_gemm<true>,  cudaFuncAttributeMaxDynamicSharedMemorySize, SMEM_G);
    cudaFuncSetAttribute(k_gemm<false>, cudaFuncAttributeMaxDynamicSharedMemorySize, SMEM_G);

    k_precomp<<<(An * CHn + 255) / 256, 256>>>(z, y, x, inv);
    k_WT<<<(APAD * CHn + 255) / 256, 256>>>(Wt, bias);
    k_gather<<<dim3(An, Bn), 256>>>(fv);
    k_transpose<<<dim3(APAD / 32, CHn / 32, Bn), dim3(32, 8)>>>();
    k_gemm<true><<<dim3(NPAD / 128, MtotPad / 128), 256, SMEM_G>>>(nullptr);
    k_softmax_attn<<<Bn * An, 256>>>();
    k_gemm<false><<<dim3(CHn / 128, APAD / 128, Bn), 256, SMEM_G>>>(out);
}

// round 10
// speedup vs baseline: 6.4704x; 1.0320x over previous
#include <cuda_runtime.h>
#include <cuda_fp16.h>
#include <cstdint>

// ---------------------------------------------------------------------------
// LaneATT — fp16 mma.sync m16n8k16, 128x256 blocks (warp 64x64), cp.async ring.
// Both GEMMs use K-major B tiles (W^T for GEMM1, feats^T for GEMM2).
//   B=32, A=1000 (pad 1024), CH=768, NSC=999 (pad 1024)
//   1) gather index; W^T -> fp16 [n][k]; padded fp32 bias
//   2) gather feats -> fp16 [b][1024][768]; transpose -> featsT [b][768][1024]
//   3) GEMM1: scores(f32, stride 1024) = feats @ W + b   (32768 x 1024, K=768)
//   4) softmax(999) -> attn fp16 [b][1024][1024], eye-shift
//   5) GEMM2: out[b] = attn[b] @ feats[b]                (1024 x 768, K=1024)
// ---------------------------------------------------------------------------

static constexpr int Bn  = 32;
static constexpr int An  = 1000;
static constexpr int APAD = 1024;
static constexpr int Cn  = 64;
static constexpr int Hn  = 12;
static constexpr int Wn  = 20;
static constexpr int CHn = Cn * Hn;        // 768
static constexpr int NSC = An - 1;         // 999
static constexpr int NPAD = 1024;
static constexpr int FVB = Cn * Hn * Wn;   // 15360
static constexpr int MtotPad = Bn * APAD;  // 32768

__device__ __half g_featsH[Bn * APAD * CHn];      // 48 MB  [b][a][ch]
__device__ __half g_featsTH[Bn * CHn * APAD];     // 48 MB  [b][ch][a]
__device__ __half g_attnH[Bn * APAD * NPAD];      // 64 MB  [b][i][j]
__device__ __half g_WTH[APAD * CHn];              // 1.5 MB [n][k]
__device__ float  g_scores[(long)MtotPad * NPAD]; // 134 MB padded stride
__device__ float  g_biasPad[NPAD];
__device__ int    g_comb[An * CHn];

// ---------------------------------------------------------------------------
__device__ __forceinline__ uint32_t smem_u32(const void* p) {
    return (uint32_t)__cvta_generic_to_shared(p);
}
__device__ __forceinline__ void cpa16(uint32_t dst, const void* src) {
    asm volatile("cp.async.cg.shared.global [%0], [%1], 16;\n" :: "r"(dst), "l"(src));
}
#define CP_COMMIT() asm volatile("cp.async.commit_group;\n" ::: "memory")
#define CP_WAIT1()  asm volatile("cp.async.wait_group 1;\n" ::: "memory")
#define CP_WAIT0()  asm volatile("cp.async.wait_group 0;\n" ::: "memory")

__device__ __forceinline__ void ldsm_x4(uint32_t* r, uint32_t addr) {
    asm volatile("ldmatrix.sync.aligned.m8n8.x4.shared.b16 {%0,%1,%2,%3}, [%4];"
                 : "=r"(r[0]), "=r"(r[1]), "=r"(r[2]), "=r"(r[3]) : "r"(addr));
}
__device__ __forceinline__ void ldsm_x2(uint32_t* r, uint32_t addr) {
    asm volatile("ldmatrix.sync.aligned.m8n8.x2.shared.b16 {%0,%1}, [%2];"
                 : "=r"(r[0]), "=r"(r[1]) : "r"(addr));
}
__device__ __forceinline__ void mma16(float* c, const uint32_t* a, const uint32_t* b) {
    asm volatile(
        "mma.sync.aligned.m16n8k16.row.col.f32.f16.f16.f32 "
        "{%0,%1,%2,%3}, {%4,%5,%6,%7}, {%8,%9}, {%0,%1,%2,%3};\n"
        : "+f"(c[0]), "+f"(c[1]), "+f"(c[2]), "+f"(c[3])
        : "r"(a[0]), "r"(a[1]), "r"(a[2]), "r"(a[3]), "r"(b[0]), "r"(b[1]));
}

// ---------------------------------------------------------------------------
// prep kernels
// ---------------------------------------------------------------------------
__global__ void k_precomp(const int* __restrict__ z, const int* __restrict__ y,
                          const int* __restrict__ x, const int* __restrict__ inv) {
    int i = blockIdx.x * blockDim.x + threadIdx.x;
    if (i >= An * CHn) return;
    g_comb[i] = inv[i] ? -1 : (z[i] * (Hn * Wn) + y[i] * Wn + x[i]);
}

__global__ void k_WT(const float* __restrict__ Wt, const float* __restrict__ bias) {
    int i = blockIdx.x * blockDim.x + threadIdx.x;
    if (i >= APAD * CHn) return;
    int n = i / CHn, k = i - n * CHn;
    g_WTH[i] = (n < NSC) ? __float2half(__ldg(Wt + (long)k * NSC + n)) : __half(0.0f);
    if (i < NPAD) g_biasPad[i] = (i < NSC) ? __ldg(bias + i) : 0.0f;
}

__global__ void k_gather(const float* __restrict__ fv) {
    int a = blockIdx.x;
    int b = blockIdx.y;
    const float* fvb = fv + b * FVB;
    const int*   cmb = g_comb + a * CHn;
    __half*      out = g_featsH + ((long)b * APAD + a) * CHn;
    for (int ch = threadIdx.x; ch < CHn; ch += blockDim.x) {
        int idx = cmb[ch];
        out[ch] = (idx < 0) ? __half(0.0f) : __float2half(__ldg(fvb + idx));
    }
}

// tiled transpose featsH -> featsTH (pad rows a>=1000 are zero; transpose too)
__global__ void k_transpose() {
    __shared__ __half t[32][40];
    int b  = blockIdx.z;
    int a0 = blockIdx.x * 32;
    int c0 = blockIdx.y * 32;
    int tx = threadIdx.x, ty = threadIdx.y;       // 32 x 8
    const __half* F  = g_featsH + (long)b * APAD * CHn;
    __half*       FT = g_featsTH + (long)b * CHn * APAD;
#pragma unroll
    for (int i = 0; i < 32; i += 8)
        t[ty + i][tx] = F[(long)(a0 + ty + i) * CHn + c0 + tx];
    __syncthreads();
#pragma unroll
    for (int i = 0; i < 32; i += 8)
        FT[(long)(c0 + ty + i) * APAD + a0 + tx] = t[tx][ty + i];
}

// ---------------------------------------------------------------------------
// GEMM: D[128 x 256] = A[128 x K] @ B[256 rows x K]^T (both K-major), fp16 in,
// fp32 accum. 8 warps (2x4), warp tile 64x64, BK=32, 3-buffer cp.async ring.
//  G1: A=featsH  lda=768,  B=WTH     ldb=768,  K=768  -> scores(+bias) padded
//  G2: A=attnH   lda=1024, B=featsTH ldb=1024, K=1024 -> out (row guard)
// ---------------------------------------------------------------------------
static constexpr int ROWB = 80;                  // smem row: 64B data + 16 pad
static constexpr int A_TB = 128 * ROWB;          // 10240
static constexpr int B_TB = 256 * ROWB;          // 20480
static constexpr int STG  = A_TB + B_TB;         // 30720
static constexpr int SMEM_G = 3 * STG;           // 92160

template <bool G1>
__global__ __launch_bounds__(256, 1) void k_gemm(float* __restrict__ out) {
    constexpr int NS = G1 ? (CHn / 32) : (APAD / 32);   // 24 / 32

    extern __shared__ char smem[];
    uint32_t sb = smem_u32(smem);

    const int tid = threadIdx.x;
    const int warp = tid >> 5, lane = tid & 31;
    const int wm = warp >> 2, wn = warp & 3;     // 2 x 4 warps -> 64x64 tiles
    const int m0 = blockIdx.y * 128;
    const int n0 = blockIdx.x * 256;

    const __half* Ag;
    const __half* Bg;
    long lda, ldb;
    if (G1) { Ag = g_featsH; Bg = g_WTH; lda = CHn; ldb = CHn; }
    else {
        int b = blockIdx.z;
        Ag = g_attnH + (long)b * APAD * NPAD;
        Bg = g_featsTH + (long)b * CHn * APAD;
        lda = NPAD; ldb = APAD;
    }

    auto load_stage = [&](int s, int buf) {
        int k0 = s * 32;
        uint32_t ab = sb + buf * STG;
        uint32_t bb = ab + A_TB;
        // A: 128 rows x 4 chunks = 512 cp.async
#pragma unroll
        for (int i = 0; i < 2; i++) {
            int idx = tid + i * 256;
            int row = idx >> 2, ch = idx & 3;
            cpa16(ab + row * ROWB + ch * 16,
                  Ag + (long)(m0 + row) * lda + k0 + ch * 8);
        }
        // B: 256 n-rows x 4 chunks = 1024 cp.async
#pragma unroll
        for (int i = 0; i < 4; i++) {
            int idx = tid + i * 256;
            int row = idx >> 2, ch = idx & 3;
            cpa16(bb + row * ROWB + ch * 16,
                  Bg + (long)(n0 + row) * ldb + k0 + ch * 8);
        }
    };

    float acc[4][8][4];
#pragma unroll
    for (int i = 0; i < 4; i++)
#pragma unroll
        for (int j = 0; j < 8; j++)
#pragma unroll
            for (int v = 0; v < 4; v++) acc[i][j][v] = 0.0f;

    load_stage(0, 0); CP_COMMIT();
    load_stage(1, 1); CP_COMMIT();

    const int l15 = lane & 15;
    const int ahi = (lane >> 4) << 4;        // +16B: k upper half for lanes 16-31
    const int bhi = ((lane >> 3) & 1) << 4;  // +16B: k upper 8 for lanes 8-15

    for (int s = 0; s < NS; s++) {
        if (s + 1 < NS) CP_WAIT1(); else CP_WAIT0();
        __syncthreads();

        uint32_t ab = sb + (s % 3) * STG;
        uint32_t bb = ab + A_TB;
#pragma unroll
        for (int kk = 0; kk < 2; kk++) {
            uint32_t af[4][4], bf[8][2];
#pragma unroll
            for (int mt = 0; mt < 4; mt++) {
                int row = wm * 64 + mt * 16 + l15;
                ldsm_x4(af[mt], ab + row * ROWB + kk * 32 + ahi);
            }
#pragma unroll
            for (int nt = 0; nt < 8; nt++) {
                int nr = wn * 64 + nt * 8 + (l15 & 7);
                ldsm_x2(bf[nt], bb + nr * ROWB + kk * 32 + bhi);
            }
#pragma unroll
            for (int mt = 0; mt < 4; mt++)
#pragma unroll
                for (int nt = 0; nt < 8; nt++)
                    mma16(acc[mt][nt], af[mt], bf[nt]);
        }

        if (s + 2 < NS) { load_stage(s + 2, (s + 2) % 3); CP_COMMIT(); }
    }

    // epilogue: c{0,1} -> (row g, cols 2t,2t+1); c{2,3} -> row g+8
    const int g = lane >> 2, t4 = lane & 3;
#pragma unroll
    for (int mt = 0; mt < 4; mt++) {
#pragma unroll
        for (int nt = 0; nt < 8; nt++) {
            int row = m0 + wm * 64 + mt * 16 + g;
            int col = n0 + wn * 64 + nt * 8 + t4 * 2;
            if (G1) {
                float2 bv = *reinterpret_cast<const float2*>(g_biasPad + col);
#pragma unroll
                for (int h = 0; h < 2; h++) {
                    float2 v = make_float2(acc[mt][nt][h * 2] + bv.x,
                                           acc[mt][nt][h * 2 + 1] + bv.y);
                    *reinterpret_cast<float2*>(
                        g_scores + (long)(row + h * 8) * NPAD + col) = v;
                }
            } else {
#pragma unroll
                for (int h = 0; h < 2; h++) {
                    int r = row + h * 8;
                    if (r < An) {
                        float2 v = make_float2(acc[mt][nt][h * 2], acc[mt][nt][h * 2 + 1]);
                        *reinterpret_cast<float2*>(
                            out + ((long)blockIdx.z * An + r) * CHn + col) = v;
                    }
                }
            }
        }
    }
}

// ---------------------------------------------------------------------------
// softmax over NSC=999 (padded scores stride 1024) -> fp16 attn row, eye-shift
// ---------------------------------------------------------------------------
__global__ __launch_bounds__(256) void k_softmax_attn() {
    int blk = blockIdx.x;
    int b = blk / An;
    int i = blk - b * An;
    const float* s = g_scores + ((long)b * APAD + i) * NPAD;
    __half* arow = g_attnH + ((long)b * APAD + i) * NPAD;
    int tid = threadIdx.x;
    __shared__ float red[8];

    float mx = -3.4e38f;
#pragma unroll
    for (int q = 0; q < 4; q++) {
        int c = tid + q * 256;
        if (c < NSC) mx = fmaxf(mx, s[c]);
    }
#pragma unroll
    for (int o = 16; o; o >>= 1) mx = fmaxf(mx, __shfl_xor_sync(0xffffffffu, mx, o));
    if ((tid & 31) == 0) red[tid >> 5] = mx;
    __syncthreads();
    mx = red[0];
#pragma unroll
    for (int w = 1; w < 8; w++) mx = fmaxf(mx, red[w]);
    __syncthreads();

    float e[4];
    float sum = 0.0f;
#pragma unroll
    for (int q = 0; q < 4; q++) {
        int c = tid + q * 256;
        float v = 0.0f;
        if (c < NSC) { v = __expf(s[c] - mx); sum += v; }
        e[q] = v;
    }
#pragma unroll
    for (int o = 16; o; o >>= 1) sum += __shfl_xor_sync(0xffffffffu, sum, o);
    if ((tid & 31) == 0) red[tid >> 5] = sum;
    __syncthreads();
    float tot = red[0];
#pragma unroll
    for (int w = 1; w < 8; w++) tot += red[w];
    float inv = 1.0f / tot;

#pragma unroll
    for (int q = 0; q < 4; q++) {
        int c = tid + q * 256;
        if (c < NSC) {
            int j = c + (c >= i ? 1 : 0);
            arow[j] = __float2half(e[q] * inv);
        }
    }
    if (tid == 0) arow[i] = __half(0.0f);
    if (tid >= 232 && tid < 256) arow[An + (tid - 232)] = __half(0.0f);  // 1000..1023
}

// ---------------------------------------------------------------------------
extern "C" void kernel_launch(void* const* d_in, const int* in_sizes, int n_in,
                              void* d_out, int out_size) {
    const float* fv   = (const float*)d_in[0];
    const int*   z    = (const int*)d_in[1];
    const int*   y    = (const int*)d_in[2];
    const int*   x    = (const int*)d_in[3];
    const int*   inv  = (const int*)d_in[4];
    const float* Wt   = (const float*)d_in[5];
    const float* bias = (const float*)d_in[6];
    float* out = (float*)d_out;

    cudaFuncSetAttribute(k_gemm<true>,  cudaFuncAttributeMaxDynamicSharedMemorySize, SMEM_G);
    cudaFuncSetAttribute(k_gemm<false>, cudaFuncAttributeMaxDynamicSharedMemorySize, SMEM_G);

    k_precomp<<<(An * CHn + 255) / 256, 256>>>(z, y, x, inv);
    k_WT<<<(APAD * CHn + 255) / 256, 256>>>(Wt, bias);
    k_gather<<<dim3(An, Bn), 256>>>(fv);
    k_transpose<<<dim3(APAD / 32, CHn / 32, Bn), dim3(32, 8)>>>();
    k_gemm<true><<<dim3(NPAD / 256, MtotPad / 128), 256, SMEM_G>>>(nullptr);
    k_softmax_attn<<<Bn * An, 256>>>();
    k_gemm<false><<<dim3(CHn / 256, APAD / 128, Bn), 256, SMEM_G>>>(out);
}

// round 11
// speedup vs baseline: 7.2322x; 1.1177x over previous
#include <cuda_runtime.h>
#include <cuda_fp16.h>
#include <cstdint>

// ---------------------------------------------------------------------------
// LaneATT — fp16 mma.sync m16n8k16, 128x256 blocks (warp 64x64), BK=64,
// 3-stage cp.async ring. K-major B tiles (W^T for GEMM1, feats^T for GEMM2).
//   B=32, A=1000 (pad 1024), CH=768, NSC=999 (pad 1024)
//   1) gather index; W^T -> fp16 [n][k]; padded fp32 bias
//   2) gather feats -> fp16 [b][1024][768]; transpose -> featsT [b][768][1024]
//   3) GEMM1: scores(f32, stride 1024) = feats @ W + b   (32768 x 1024, K=768)
//   4) softmax(999) -> attn fp16 [b][1024][1024], eye-shift (float4 one-shot)
//   5) GEMM2: out[b] = attn[b] @ feats[b]                (1024 x 768, K=1024)
// ---------------------------------------------------------------------------

static constexpr int Bn  = 32;
static constexpr int An  = 1000;
static constexpr int APAD = 1024;
static constexpr int Cn  = 64;
static constexpr int Hn  = 12;
static constexpr int Wn  = 20;
static constexpr int CHn = Cn * Hn;        // 768
static constexpr int NSC = An - 1;         // 999
static constexpr int NPAD = 1024;
static constexpr int FVB = Cn * Hn * Wn;   // 15360
static constexpr int MtotPad = Bn * APAD;  // 32768

__device__ __half g_featsH[Bn * APAD * CHn];      // 48 MB  [b][a][ch]
__device__ __half g_featsTH[Bn * CHn * APAD];     // 48 MB  [b][ch][a]
__device__ __half g_attnH[Bn * APAD * NPAD];      // 64 MB  [b][i][j]
__device__ __half g_WTH[APAD * CHn];              // 1.5 MB [n][k]
__device__ float  g_scores[(long)MtotPad * NPAD]; // 134 MB padded stride
__device__ float  g_biasPad[NPAD];
__device__ int    g_comb[An * CHn];

// ---------------------------------------------------------------------------
__device__ __forceinline__ uint32_t smem_u32(const void* p) {
    return (uint32_t)__cvta_generic_to_shared(p);
}
__device__ __forceinline__ void cpa16(uint32_t dst, const void* src) {
    asm volatile("cp.async.cg.shared.global [%0], [%1], 16;\n" :: "r"(dst), "l"(src));
}
#define CP_COMMIT() asm volatile("cp.async.commit_group;\n" ::: "memory")
#define CP_WAIT1()  asm volatile("cp.async.wait_group 1;\n" ::: "memory")
#define CP_WAIT0()  asm volatile("cp.async.wait_group 0;\n" ::: "memory")

__device__ __forceinline__ void ldsm_x4(uint32_t* r, uint32_t addr) {
    asm volatile("ldmatrix.sync.aligned.m8n8.x4.shared.b16 {%0,%1,%2,%3}, [%4];"
                 : "=r"(r[0]), "=r"(r[1]), "=r"(r[2]), "=r"(r[3]) : "r"(addr));
}
__device__ __forceinline__ void ldsm_x2(uint32_t* r, uint32_t addr) {
    asm volatile("ldmatrix.sync.aligned.m8n8.x2.shared.b16 {%0,%1}, [%2];"
                 : "=r"(r[0]), "=r"(r[1]) : "r"(addr));
}
__device__ __forceinline__ void mma16(float* c, const uint32_t* a, const uint32_t* b) {
    asm volatile(
        "mma.sync.aligned.m16n8k16.row.col.f32.f16.f16.f32 "
        "{%0,%1,%2,%3}, {%4,%5,%6,%7}, {%8,%9}, {%0,%1,%2,%3};\n"
        : "+f"(c[0]), "+f"(c[1]), "+f"(c[2]), "+f"(c[3])
        : "r"(a[0]), "r"(a[1]), "r"(a[2]), "r"(a[3]), "r"(b[0]), "r"(b[1]));
}

// ---------------------------------------------------------------------------
// prep kernels
// ---------------------------------------------------------------------------
__global__ void k_precomp(const int* __restrict__ z, const int* __restrict__ y,
                          const int* __restrict__ x, const int* __restrict__ inv) {
    int i = blockIdx.x * blockDim.x + threadIdx.x;
    if (i >= An * CHn) return;
    g_comb[i] = inv[i] ? -1 : (z[i] * (Hn * Wn) + y[i] * Wn + x[i]);
}

__global__ void k_WT(const float* __restrict__ Wt, const float* __restrict__ bias) {
    int i = blockIdx.x * blockDim.x + threadIdx.x;
    if (i >= APAD * CHn) return;
    int n = i / CHn, k = i - n * CHn;
    g_WTH[i] = (n < NSC) ? __float2half(__ldg(Wt + (long)k * NSC + n)) : __half(0.0f);
    if (i < NPAD) g_biasPad[i] = (i < NSC) ? __ldg(bias + i) : 0.0f;
}

__global__ void k_gather(const float* __restrict__ fv) {
    int a = blockIdx.x;
    int b = blockIdx.y;
    const float* fvb = fv + b * FVB;
    const int*   cmb = g_comb + a * CHn;
    __half2*     out = reinterpret_cast<__half2*>(g_featsH + ((long)b * APAD + a) * CHn);
    for (int p = threadIdx.x; p < CHn / 2; p += blockDim.x) {
        int i0 = cmb[2 * p], i1 = cmb[2 * p + 1];
        float f0 = (i0 < 0) ? 0.0f : __ldg(fvb + i0);
        float f1 = (i1 < 0) ? 0.0f : __ldg(fvb + i1);
        out[p] = __floats2half2_rn(f0, f1);
    }
}

// tiled transpose featsH -> featsTH (pad rows a>=1000 are zero; transpose too)
__global__ void k_transpose() {
    __shared__ __half t[32][40];
    int b  = blockIdx.z;
    int a0 = blockIdx.x * 32;
    int c0 = blockIdx.y * 32;
    int tx = threadIdx.x, ty = threadIdx.y;       // 32 x 8
    const __half* F  = g_featsH + (long)b * APAD * CHn;
    __half*       FT = g_featsTH + (long)b * CHn * APAD;
#pragma unroll
    for (int i = 0; i < 32; i += 8)
        t[ty + i][tx] = F[(long)(a0 + ty + i) * CHn + c0 + tx];
    __syncthreads();
#pragma unroll
    for (int i = 0; i < 32; i += 8)
        FT[(long)(c0 + ty + i) * APAD + a0 + tx] = t[tx][ty + i];
}

// ---------------------------------------------------------------------------
// GEMM: D[128 x 256] = A[128 x K] @ B[256 rows x K]^T (both K-major), fp16 in,
// fp32 accum. 8 warps (2x4), warp tile 64x64, BK=64, 3-stage cp.async ring.
//  G1: A=featsH  lda=768,  B=WTH     ldb=768,  K=768  -> scores(+bias) padded
//  G2: A=attnH   lda=1024, B=featsTH ldb=1024, K=1024 -> out (row guard)
// ---------------------------------------------------------------------------
static constexpr int ROWB = 144;                 // smem row: 128B data + 16 pad
static constexpr int A_TB = 128 * ROWB;          // 18432
static constexpr int B_TB = 256 * ROWB;          // 36864
static constexpr int STG  = A_TB + B_TB;         // 55296
static constexpr int SMEM_G = 3 * STG;           // 165888

template <bool G1>
__global__ __launch_bounds__(256, 1) void k_gemm(float* __restrict__ out) {
    constexpr int NS = G1 ? (CHn / 64) : (APAD / 64);   // 12 / 16

    extern __shared__ char smem[];
    uint32_t sb = smem_u32(smem);

    const int tid = threadIdx.x;
    const int warp = tid >> 5, lane = tid & 31;
    const int wm = warp >> 2, wn = warp & 3;     // 2 x 4 warps -> 64x64 tiles
    const int m0 = blockIdx.y * 128;
    const int n0 = blockIdx.x * 256;

    const __half* Ag;
    const __half* Bg;
    long lda, ldb;
    if (G1) { Ag = g_featsH; Bg = g_WTH; lda = CHn; ldb = CHn; }
    else {
        int b = blockIdx.z;
        Ag = g_attnH + (long)b * APAD * NPAD;
        Bg = g_featsTH + (long)b * CHn * APAD;
        lda = NPAD; ldb = APAD;
    }

    auto load_stage = [&](int s, int buf) {
        int k0 = s * 64;
        uint32_t ab = sb + buf * STG;
        uint32_t bb = ab + A_TB;
        // A: 128 rows x 8 chunks = 1024 cp.async
#pragma unroll
        for (int i = 0; i < 4; i++) {
            int idx = tid + i * 256;
            int row = idx >> 3, ch = idx & 7;
            cpa16(ab + row * ROWB + ch * 16,
                  Ag + (long)(m0 + row) * lda + k0 + ch * 8);
        }
        // B: 256 n-rows x 8 chunks = 2048 cp.async
#pragma unroll
        for (int i = 0; i < 8; i++) {
            int idx = tid + i * 256;
            int row = idx >> 3, ch = idx & 7;
            cpa16(bb + row * ROWB + ch * 16,
                  Bg + (long)(n0 + row) * ldb + k0 + ch * 8);
        }
    };

    float acc[4][8][4];
#pragma unroll
    for (int i = 0; i < 4; i++)
#pragma unroll
        for (int j = 0; j < 8; j++)
#pragma unroll
            for (int v = 0; v < 4; v++) acc[i][j][v] = 0.0f;

    load_stage(0, 0); CP_COMMIT();
    load_stage(1, 1); CP_COMMIT();

    const int l15 = lane & 15;
    const int ahi = (lane >> 4) << 4;        // +16B: k upper half for lanes 16-31
    const int bhi = ((lane >> 3) & 1) << 4;  // +16B: k upper 8 for lanes 8-15

    for (int s = 0; s < NS; s++) {
        if (s + 1 < NS) CP_WAIT1(); else CP_WAIT0();
        __syncthreads();

        uint32_t ab = sb + (s % 3) * STG;
        uint32_t bb = ab + A_TB;
#pragma unroll
        for (int kk = 0; kk < 4; kk++) {
            uint32_t af[4][4], bf[8][2];
#pragma unroll
            for (int mt = 0; mt < 4; mt++) {
                int row = wm * 64 + mt * 16 + l15;
                ldsm_x4(af[mt], ab + row * ROWB + kk * 32 + ahi);
            }
#pragma unroll
            for (int nt = 0; nt < 8; nt++) {
                int nr = wn * 64 + nt * 8 + (l15 & 7);
                ldsm_x2(bf[nt], bb + nr * ROWB + kk * 32 + bhi);
            }
#pragma unroll
            for (int mt = 0; mt < 4; mt++)
#pragma unroll
                for (int nt = 0; nt < 8; nt++)
                    mma16(acc[mt][nt], af[mt], bf[nt]);
        }

        if (s + 2 < NS) { load_stage(s + 2, (s + 2) % 3); CP_COMMIT(); }
    }

    // epilogue: c{0,1} -> (row g, cols 2t,2t+1); c{2,3} -> row g+8
    const int g = lane >> 2, t4 = lane & 3;
#pragma unroll
    for (int mt = 0; mt < 4; mt++) {
#pragma unroll
        for (int nt = 0; nt < 8; nt++) {
            int row = m0 + wm * 64 + mt * 16 + g;
            int col = n0 + wn * 64 + nt * 8 + t4 * 2;
            if (G1) {
                float2 bv = *reinterpret_cast<const float2*>(g_biasPad + col);
#pragma unroll
                for (int h = 0; h < 2; h++) {
                    float2 v = make_float2(acc[mt][nt][h * 2] + bv.x,
                                           acc[mt][nt][h * 2 + 1] + bv.y);
                    *reinterpret_cast<float2*>(
                        g_scores + (long)(row + h * 8) * NPAD + col) = v;
                }
            } else {
#pragma unroll
                for (int h = 0; h < 2; h++) {
                    int r = row + h * 8;
                    if (r < An) {
                        float2 v = make_float2(acc[mt][nt][h * 2], acc[mt][nt][h * 2 + 1]);
                        *reinterpret_cast<float2*>(
                            out + ((long)blockIdx.z * An + r) * CHn + col) = v;
                    }
                }
            }
        }
    }
}

// ---------------------------------------------------------------------------
// softmax over NSC=999 -> fp16 attn row with eye-shift.
// 256 threads x one float4 over the padded 1024-row; tail masked in registers.
// ---------------------------------------------------------------------------
__global__ __launch_bounds__(256) void k_softmax_attn() {
    int blk = blockIdx.x;
    int b = blk / An;
    int i = blk - b * An;
    const float* s = g_scores + ((long)b * APAD + i) * NPAD;
    __half* arow = g_attnH + ((long)b * APAD + i) * NPAD;
    int tid = threadIdx.x;
    __shared__ float red[8];

    const int c4 = tid * 4;
    float4 v = *reinterpret_cast<const float4*>(s + c4);   // padded: always safe
    float vv[4] = { v.x, v.y, v.z, v.w };

    // max over valid elems
    float mx = -3.4e38f;
#pragma unroll
    for (int e = 0; e < 4; e++)
        if (c4 + e < NSC) mx = fmaxf(mx, vv[e]);
#pragma unroll
    for (int o = 16; o; o >>= 1) mx = fmaxf(mx, __shfl_xor_sync(0xffffffffu, mx, o));
    if ((tid & 31) == 0) red[tid >> 5] = mx;
    __syncthreads();
    mx = red[0];
#pragma unroll
    for (int w = 1; w < 8; w++) mx = fmaxf(mx, red[w]);
    __syncthreads();

    // exp + sum
    float ex[4];
    float sum = 0.0f;
#pragma unroll
    for (int e = 0; e < 4; e++) {
        float t = 0.0f;
        if (c4 + e < NSC) { t = __expf(vv[e] - mx); sum += t; }
        ex[e] = t;
    }
#pragma unroll
    for (int o = 16; o; o >>= 1) sum += __shfl_xor_sync(0xffffffffu, sum, o);
    if ((tid & 31) == 0) red[tid >> 5] = sum;
    __syncthreads();
    float tot = red[0];
#pragma unroll
    for (int w = 1; w < 8; w++) tot += red[w];
    float inv = 1.0f / tot;

    // write with eye-shift; no thread writes arow[i] (j==i unreachable)
#pragma unroll
    for (int e = 0; e < 4; e++) {
        int c = c4 + e;
        if (c < NSC) {
            int j = c + (c >= i ? 1 : 0);
            arow[j] = __float2half(ex[e] * inv);
        }
    }
    if (tid == 0) arow[i] = __half(0.0f);
    if (tid >= 250) {                          // zero cols 1000..1023
        int c = 1000 + (tid - 250) * 4;
#pragma unroll
        for (int e = 0; e < 4; e++) arow[c + e] = __half(0.0f);
    }
}

// ---------------------------------------------------------------------------
extern "C" void kernel_launch(void* const* d_in, const int* in_sizes, int n_in,
                              void* d_out, int out_size) {
    const float* fv   = (const float*)d_in[0];
    const int*   z    = (const int*)d_in[1];
    const int*   y    = (const int*)d_in[2];
    const int*   x    = (const int*)d_in[3];
    const int*   inv  = (const int*)d_in[4];
    const float* Wt   = (const float*)d_in[5];
    const float* bias = (const float*)d_in[6];
    float* out = (float*)d_out;

    cudaFuncSetAttribute(k_gemm<true>,  cudaFuncAttributeMaxDynamicSharedMemorySize, SMEM_G);
    cudaFuncSetAttribute(k_gemm<false>, cudaFuncAttributeMaxDynamicSharedMemorySize, SMEM_G);

    k_precomp<<<(An * CHn + 255) / 256, 256>>>(z, y, x, inv);
    k_WT<<<(APAD * CHn + 255) / 256, 256>>>(Wt, bias);
    k_gather<<<dim3(An, Bn), 256>>>(fv);
    k_transpose<<<dim3(APAD / 32, CHn / 32, Bn), dim3(32, 8)>>>();
    k_gemm<true><<<dim3(NPAD / 256, MtotPad / 128), 256, SMEM_G>>>(nullptr);
    k_softmax_attn<<<Bn * An, 256>>>();
    k_gemm<false><<<dim3(CHn / 256, APAD / 128, Bn), 256, SMEM_G>>>(out);
}